// round 5
// baseline (speedup 1.0000x reference)
#include <cuda_runtime.h>
#include <math.h>

#define BB 16
#define LL 512
#define DD 768
#define HH 4
#define AA 100
#define DK 25
#define PP 3
#define EPS 1e-6f

#define BM 32
#define BN 112
#define AST 20
#define BST 20
#define BNNST 120
#define NSTG 3

// ---------------- scratch ----------------
__device__ float g_seqn[BB * LL * DD];
__device__ float g_feats[BB * LL * 3 * AA];   // [x | x1 | x2], row stride 300
__device__ float g_qk  [BB * LL * 2 * AA];    // [q | k], row stride 200
__device__ float g_qkw [2 * AA * AA];
__device__ float g_qkb [2 * AA];
__device__ float g_adjm[(size_t)BB * LL * LL];
__device__ float g_adjc[(size_t)BB * LL * LL];
__device__ float g_Ax  [BB * LL * AA];
__device__ float g_node[BB * LL * AA];
__device__ float g_pooled[BB * AA];
__device__ float g_cbuf[HH];
__device__ float g_b1m[AA];
__device__ float g_b2m[AA];
__device__ float g_bm[1];
__device__ float g_vm[BB * LL];
__device__ float g_S[BB * AA];
__device__ float g_U[BB * AA];

__device__ __forceinline__ unsigned tf32cvt(float x) {
    unsigned u;
    asm("cvt.rna.tf32.f32 %0, %1;" : "=r"(u) : "f"(x));
    return u;
}
__device__ __forceinline__ void mma_tf32(float* c, unsigned a0, unsigned a1,
                                         unsigned a2, unsigned a3,
                                         unsigned b0, unsigned b1) {
    asm volatile(
        "mma.sync.aligned.m16n8k8.row.col.f32.tf32.tf32.f32 "
        "{%0,%1,%2,%3}, {%4,%5,%6,%7}, {%8,%9}, {%0,%1,%2,%3};"
        : "+f"(c[0]), "+f"(c[1]), "+f"(c[2]), "+f"(c[3])
        : "r"(a0), "r"(a1), "r"(a2), "r"(a3), "r"(b0), "r"(b1));
}
__device__ __forceinline__ void cp16(unsigned dst, const void* src, int bytes) {
    asm volatile("cp.async.cg.shared.global [%0], [%1], 16, %2;\n"
                 :: "r"(dst), "l"(src), "r"(bytes));
}
__device__ __forceinline__ void cp_commit() { asm volatile("cp.async.commit_group;\n"); }
__device__ __forceinline__ void cp_wait1()  { asm volatile("cp.async.wait_group 1;\n"); }

// ---------------- precompute + qk weight packing ----------------
__global__ void pre_kernel(const float* __restrict__ Wx_w, const float* __restrict__ Wx_b,
                           const float* __restrict__ q_w, const float* __restrict__ q_b,
                           const float* __restrict__ k_w, const float* __restrict__ k_b)
{
    int t = threadIdx.x;
    int idx = blockIdx.x * 256 + t;
    if (idx < 2 * AA * AA) {
        int r = idx / AA, c = idx - r * AA;
        g_qkw[idx] = (r < AA) ? q_w[r * AA + c] : k_w[(r - AA) * AA + c];
    }
    if (blockIdx.x == 0) {
        const int LDW = HH + 2 * AA;
        if (t < 2 * AA) g_qkb[t] = (t < AA) ? q_b[t] : k_b[t - AA];
        if (t < HH) {
            float s = 0.f;
            for (int g = 0; g < HH; g++) s += Wx_w[g * LDW + t];
            g_cbuf[t] = s * 0.25f;
        }
        if (t < AA) {
            float s1 = 0.f, s2 = 0.f;
            for (int g = 0; g < HH; g++) {
                s1 += Wx_w[g * LDW + HH + t];
                s2 += Wx_w[g * LDW + HH + AA + t];
            }
            g_b1m[t] = s1 * 0.25f;
            g_b2m[t] = s2 * 0.25f;
        }
        if (t == 0) {
            float s = 0.f;
            for (int g = 0; g < HH; g++) s += Wx_b[g];
            g_bm[0] = s * 0.25f;
        }
    }
}

// ---------------- LayerNorm ----------------
__global__ void ln_kernel(const float* __restrict__ x, const float* __restrict__ a,
                          const float* __restrict__ bvec)
{
    int row = blockIdx.x;
    const float* xr = x + (size_t)row * DD;
    float* yr = g_seqn + (size_t)row * DD;
    int t = threadIdx.x;
    __shared__ float red[16];
    float v0 = xr[t], v1 = xr[t + 256], v2 = xr[t + 512];
    float s = v0 + v1 + v2;
    float ss = v0 * v0 + v1 * v1 + v2 * v2;
    for (int o = 16; o; o >>= 1) {
        s  += __shfl_xor_sync(0xffffffffu, s, o);
        ss += __shfl_xor_sync(0xffffffffu, ss, o);
    }
    int w = t >> 5;
    if ((t & 31) == 0) { red[w] = s; red[8 + w] = ss; }
    __syncthreads();
    float S = 0.f, SS = 0.f;
    #pragma unroll
    for (int i = 0; i < 8; i++) { S += red[i]; SS += red[8 + i]; }
    float mean = S / (float)DD;
    float var = (SS - (float)DD * mean * mean) / (float)(DD - 1);
    var = fmaxf(var, 0.f);
    float inv = 1.f / (sqrtf(var) + EPS);
    yr[t]       = a[t]       * (v0 - mean) * inv + bvec[t];
    yr[t + 256] = a[t + 256] * (v1 - mean) * inv + bvec[t + 256];
    yr[t + 512] = a[t + 512] * (v2 - mean) * inv + bvec[t + 512];
}

// ============ TF32 NT GEMM: C = act(A(M,K; lda) @ B(N,K)^T + bias), ldc ============
__global__ __launch_bounds__(128) void gemm_nt_tc(
    const float* __restrict__ A, int lda,
    const float* __restrict__ Bw, const float* __restrict__ bias,
    float* __restrict__ C, int ldc,
    int M, int N, int K, int act)
{
    __shared__ float As[NSTG][BM * AST];
    __shared__ float Bs[NSTG][BN * BST];
    int t = threadIdx.x;
    int lane = t & 31, warp = t >> 5;
    int wm = warp & 1, wn = warp >> 1;
    int g = lane >> 2, tg = lane & 3;
    int m0 = blockIdx.y * BM, n0 = blockIdx.x * BN;

    unsigned sA = (unsigned)__cvta_generic_to_shared(&As[0][0]);
    unsigned sB = (unsigned)__cvta_generic_to_shared(&Bs[0][0]);

    float acc[7][4];
    #pragma unroll
    for (int j = 0; j < 7; j++)
        #pragma unroll
        for (int i = 0; i < 4; i++) acc[j][i] = 0.f;

    const int arow = t >> 2, ac4 = (t & 3) * 4;
    int nk = (K + 15) >> 4;

    auto issue = [&](int p) {
        int k0 = p << 4;
        int s = p % NSTG;
        int rem = (K - k0 - ac4) * 4;
        int bytes = rem >= 16 ? 16 : (rem > 0 ? rem : 0);
        cp16(sA + (s * BM * AST + arow * AST + ac4) * 4,
             A + (size_t)(m0 + arow) * lda + k0 + ac4, bytes);
        #pragma unroll
        for (int i = 0; i < 4; i++) {
            int idx = t + i * 128;
            if (idx < BN * 4) {
                int row = idx >> 2, c = idx & 3;
                int rem2 = (K - k0 - c * 4) * 4;
                int brow = n0 + row;
                int bytes2 = (brow < N) ? (rem2 >= 16 ? 16 : (rem2 > 0 ? rem2 : 0)) : 0;
                cp16(sB + (s * BN * BST + row * BST + c * 4) * 4,
                     Bw + (size_t)(brow < N ? brow : 0) * K + k0 + c * 4, bytes2);
            }
        }
    };

    issue(0); cp_commit();
    if (nk > 1) issue(1);
    cp_commit();

    for (int it = 0; it < nk; it++) {
        cp_wait1();
        __syncthreads();
        if (it + 2 < nk) issue(it + 2);
        cp_commit();
        int s = it % NSTG;
        const float* as = &As[s][0];
        const float* bs = &Bs[s][0];
        #pragma unroll
        for (int kb = 0; kb < 16; kb += 8) {
            int ar = (wm * 16 + g) * AST + kb + tg;
            unsigned a0 = tf32cvt(as[ar]);
            unsigned a1 = tf32cvt(as[ar + 8 * AST]);
            unsigned a2 = tf32cvt(as[ar + 4]);
            unsigned a3 = tf32cvt(as[ar + 8 * AST + 4]);
            #pragma unroll
            for (int j = 0; j < 7; j++) {
                int br = (wn * 56 + j * 8 + g) * BST + kb + tg;
                unsigned b0 = tf32cvt(bs[br]);
                unsigned b1 = tf32cvt(bs[br + 4]);
                mma_tf32(acc[j], a0, a1, a2, a3, b0, b1);
            }
        }
    }

    int r0 = m0 + wm * 16 + g, r1 = r0 + 8;
    #pragma unroll
    for (int j = 0; j < 7; j++) {
        #pragma unroll
        for (int jj = 0; jj < 2; jj++) {
            int col = n0 + wn * 56 + j * 8 + tg * 2 + jj;
            if (col >= N) continue;
            float bv = bias[col];
            float v0 = acc[j][jj] + bv, v1 = acc[j][2 + jj] + bv;
            if (act) { v0 = fmaxf(v0, 0.f); v1 = fmaxf(v1, 0.f); }
            C[(size_t)r0 * ldc + col] = v0;
            C[(size_t)r1 * ldc + col] = v1;
        }
    }
}

// ============ TF32 batched NN GEMM: C[b] = A[b](512,512) @ B[b](512,N; ldb) + rank-1 ============
__global__ __launch_bounds__(128) void gemm_nn_b_tc(
    const float* __restrict__ Ag, const float* __restrict__ Bg, int ldb, int sB,
    float* __restrict__ Cg, int ldc, int sC, int N,
    const float* __restrict__ U, const float* __restrict__ S,
    const float* __restrict__ vm, const float* __restrict__ bmp)
{
    const int K = LL;
    int b = blockIdx.z;
    const float* A = Ag + (size_t)b * LL * LL;
    const float* Bm = Bg + (size_t)b * sB;
    float* C = Cg + (size_t)b * sC;
    __shared__ float As[NSTG][BM * AST];
    __shared__ float Bs[NSTG][16 * BNNST];
    int t = threadIdx.x;
    int lane = t & 31, warp = t >> 5;
    int wm = warp & 1, wn = warp >> 1;
    int g = lane >> 2, tg = lane & 3;
    int m0 = blockIdx.y * BM;

    unsigned sA = (unsigned)__cvta_generic_to_shared(&As[0][0]);
    unsigned sBs = (unsigned)__cvta_generic_to_shared(&Bs[0][0]);

    float acc[7][4];
    #pragma unroll
    for (int j = 0; j < 7; j++)
        #pragma unroll
        for (int i = 0; i < 4; i++) acc[j][i] = 0.f;

    const int arow = t >> 2, ac4 = (t & 3) * 4;
    int nk = K >> 4;

    auto issue = [&](int p) {
        int k0 = p << 4;
        int s = p % NSTG;
        cp16(sA + (s * BM * AST + arow * AST + ac4) * 4,
             A + (size_t)(m0 + arow) * K + k0 + ac4, 16);
        #pragma unroll
        for (int i = 0; i < 4; i++) {
            int idx = t + i * 128;
            if (idx < 448) {
                int k = idx / 28, c = idx - k * 28;
                int bytes = (c * 4 < N) ? ((N - c * 4) >= 4 ? 16 : (N - c * 4) * 4) : 0;
                cp16(sBs + (s * 16 * BNNST + k * BNNST + c * 4) * 4,
                     Bm + (size_t)(k0 + k) * ldb + c * 4, bytes);
            }
        }
    };

    issue(0); cp_commit();
    issue(1); cp_commit();

    for (int it = 0; it < nk; it++) {
        cp_wait1();
        __syncthreads();
        if (it + 2 < nk) issue(it + 2);
        cp_commit();
        int s = it % NSTG;
        const float* as = &As[s][0];
        const float* bs = &Bs[s][0];
        #pragma unroll
        for (int kb = 0; kb < 16; kb += 8) {
            int ar = (wm * 16 + g) * AST + kb + tg;
            unsigned a0 = tf32cvt(as[ar]);
            unsigned a1 = tf32cvt(as[ar + 8 * AST]);
            unsigned a2 = tf32cvt(as[ar + 4]);
            unsigned a3 = tf32cvt(as[ar + 8 * AST + 4]);
            #pragma unroll
            for (int j = 0; j < 7; j++) {
                int bcol = wn * 56 + j * 8 + g;
                unsigned b0 = tf32cvt(bs[(kb + tg) * BNNST + bcol]);
                unsigned b1 = tf32cvt(bs[(kb + tg + 4) * BNNST + bcol]);
                mma_tf32(acc[j], a0, a1, a2, a3, b0, b1);
            }
        }
    }

    int r0 = m0 + wm * 16 + g, r1 = r0 + 8;
    float e0 = 0.f, e1 = 0.f;
    if (U != nullptr) {
        float bmv = bmp[0];
        e0 = vm[b * LL + r0] + bmv;
        e1 = vm[b * LL + r1] + bmv;
    }
    #pragma unroll
    for (int j = 0; j < 7; j++) {
        #pragma unroll
        for (int jj = 0; jj < 2; jj++) {
            int col = wn * 56 + j * 8 + tg * 2 + jj;
            if (col >= N) continue;
            float v0 = acc[j][jj], v1 = acc[j][2 + jj];
            if (U != nullptr) {
                float uu = U[b * AA + col], ssv = S[b * AA + col];
                v0 += uu + e0 * ssv;
                v1 += uu + e1 * ssv;
            }
            C[(size_t)r0 * ldc + col] = v0;
            C[(size_t)r1 * ldc + col] = v1;
        }
    }
}

// ============ fused scores + softmax + head folding ============
// grid (32, 16): blockIdx.x = 16-row i tile, blockIdx.y = b. 256 threads.
// thread: row = t&15, jgroup = t>>4 -> lanes 0-15 read same k_j (smem broadcast)
__global__ __launch_bounds__(256, 2) void attn_kernel(
    const float* __restrict__ syn, const int* __restrict__ src_mask)
{
    extern __shared__ float sm[];
    float* ks  = sm;                    // 512*28
    float* qs  = sm + 512 * 28;         // 16*28
    float* mk  = qs + 16 * 28;          // 512
    float* red = mk + 512;              // 16*9

    int b = blockIdx.y;
    int i0 = blockIdx.x * 16;
    int t = threadIdx.x;
    int row = t & 15;
    int jg  = t >> 4;
    int lane = t & 31, w = t >> 5;

    // zero pads once (stay zero; loads only touch c<25)
    for (int idx = t; idx < 512 * 3; idx += 256) {
        int j = idx / 3, c = idx - j * 3;
        ks[j * 28 + 25 + c] = 0.f;
    }
    if (t < 48) { int i = t / 3, c = t - (t / 3) * 3; qs[i * 28 + 25 + c] = 0.f; }
    for (int j = t; j < 512; j += 256) mk[j] = src_mask[b * LL + j] ? 0.f : -1e9f;

    float am[32], ac[32];
    #pragma unroll
    for (int jj = 0; jj < 32; jj++) { am[jj] = 0.f; ac[jj] = 0.f; }

    for (int h = 0; h < HH; h++) {
        __syncthreads();
        for (int idx = t; idx < 512 * 25; idx += 256) {
            int j = idx / 25, c = idx - j * 25;
            ks[j * 28 + c] = g_qk[((size_t)b * LL + j) * 200 + 100 + h * 25 + c];
        }
        if (t < 400) {
            int i = t / 25, c = t - (t / 25) * 25;
            qs[i * 28 + c] = g_qk[((size_t)b * LL + i0 + i) * 200 + h * 25 + c];
        }
        __syncthreads();

        float4 q4[7];
        #pragma unroll
        for (int c = 0; c < 7; c++) q4[c] = ((const float4*)(qs + row * 28))[c];
        const float* synrow = syn + (((size_t)(b * HH + h)) * LL + (i0 + row)) * LL;

        float sc[32];
        float m = -1e30f;
        #pragma unroll
        for (int jj = 0; jj < 32; jj++) {
            int j = jg * 32 + jj;
            const float4* kp = (const float4*)(ks + j * 28);
            float s = 0.f;
            #pragma unroll
            for (int c = 0; c < 7; c++) {
                float4 k4 = kp[c];
                s += q4[c].x * k4.x + q4[c].y * k4.y + q4[c].z * k4.z + q4[c].w * k4.w;
            }
            float v = s * 0.2f + mk[j] + synrow[j];
            sc[jj] = v;
            m = fmaxf(m, v);
        }
        m = fmaxf(m, __shfl_xor_sync(0xffffffffu, m, 16));
        if (lane < 16) red[row * 9 + w] = m;
        __syncthreads();
        m = red[row * 9];
        #pragma unroll
        for (int k = 1; k < 8; k++) m = fmaxf(m, red[row * 9 + k]);

        float sum = 0.f;
        #pragma unroll
        for (int jj = 0; jj < 32; jj++) {
            float e = __expf(sc[jj] - m);
            sc[jj] = e;
            sum += e;
        }
        sum += __shfl_xor_sync(0xffffffffu, sum, 16);
        __syncthreads();
        if (lane < 16) red[row * 9 + w] = sum;
        __syncthreads();
        sum = 0.f;
        #pragma unroll
        for (int k = 0; k < 8; k++) sum += red[row * 9 + k];

        float inv = 1.f / sum;
        float ch = g_cbuf[h];
        #pragma unroll
        for (int jj = 0; jj < 32; jj++) {
            float p = sc[jj] * inv;
            am[jj] += 0.25f * p;
            ac[jj] += ch * p;
        }
    }

    // transpose through smem for coalesced stores
    float* tb = ks;  // 16*513 = 8208 <= 14336
    __syncthreads();
    #pragma unroll
    for (int jj = 0; jj < 32; jj++) tb[row * 513 + jg * 32 + jj] = am[jj];
    __syncthreads();
    for (int idx = t; idx < 8192; idx += 256) {
        int r = idx >> 9, j = idx & 511;
        g_adjm[((size_t)(b * LL) + i0 + r) * LL + j] = tb[r * 513 + j];
    }
    __syncthreads();
    #pragma unroll
    for (int jj = 0; jj < 32; jj++) tb[row * 513 + jg * 32 + jj] = ac[jj];
    __syncthreads();
    for (int idx = t; idx < 8192; idx += 256) {
        int r = idx >> 9, j = idx & 511;
        g_adjc[((size_t)(b * LL) + i0 + r) * LL + j] = tb[r * 513 + j];
    }
}

// ---------------- merged um/vm + S/U (block per batch) ----------------
__global__ void umvm_su_kernel()
{
    int b = blockIdx.x, t = threadIdx.x, w = t >> 5, lane = t & 31;
    __shared__ float su[LL];
    for (int r = w; r < LL; r += 8) {
        const float* xr = g_feats + ((size_t)(b * LL + r)) * 300 + 100;
        float u = 0.f, v = 0.f;
        for (int c = lane; c < AA; c += 32) {
            float xv = xr[c];
            u += xv * g_b1m[c];
            v += xv * g_b2m[c];
        }
        for (int o = 16; o; o >>= 1) {
            u += __shfl_xor_sync(0xffffffffu, u, o);
            v += __shfl_xor_sync(0xffffffffu, v, o);
        }
        if (lane == 0) { su[r] = u; g_vm[b * LL + r] = v; }
    }
    __syncthreads();
    if (t < AA) {
        float s = 0.f, u = 0.f;
        for (int j = 0; j < LL; j++) {
            float xv = g_feats[((size_t)(b * LL + j)) * 300 + 100 + t];
            s += xv;
            u += su[j] * xv;
        }
        g_S[b * AA + t] = s;
        g_U[b * AA + t] = u;
    }
}

// ---------------- pool ----------------
__global__ void pool_kernel(const int* __restrict__ mask_ids)
{
    int b = blockIdx.x;
    __shared__ int redc[128];
    int t = threadIdx.x;
    int cnt = 0;
    for (int j = t; j < LL; j += 128) cnt += mask_ids[b * LL + j];
    redc[t] = cnt;
    __syncthreads();
    for (int o = 64; o; o >>= 1) { if (t < o) redc[t] += redc[t + o]; __syncthreads(); }
    float vl = fmaxf((float)redc[0], 1.f);
    if (t < AA) {
        float s = 0.f;
        for (int j = 0; j < LL; j++) s += g_node[(size_t)(b * LL + j) * AA + t];
        g_pooled[b * AA + t] = s / vl;
    }
}

// ---------------- logits ----------------
__global__ void logits_kernel(const float* __restrict__ cw, const float* __restrict__ cb,
                              float* __restrict__ out)
{
    int t = threadIdx.x;
    if (t >= BB * PP) return;
    int b = t / PP, p = t % PP;
    float s = cb[p];
    for (int d = 0; d < AA; d++) s += g_pooled[b * AA + d] * cw[p * AA + d];
    out[t] = s;
}

// ================================================================
extern "C" void kernel_launch(void* const* d_in, const int* in_sizes, int n_in,
                              void* d_out, int out_size)
{
    const float* seq     = (const float*)d_in[0];
    const float* syn     = (const float*)d_in[1];
    const float* ln_a    = (const float*)d_in[2];
    const float* ln_b    = (const float*)d_in[3];
    const float* Wxx_w   = (const float*)d_in[4];
    const float* Wxx_b   = (const float*)d_in[5];
    const float* q_w     = (const float*)d_in[6];
    const float* q_b     = (const float*)d_in[7];
    const float* k_w     = (const float*)d_in[8];
    const float* k_b     = (const float*)d_in[9];
    const float* W_w     = (const float*)d_in[10];
    const float* W_b     = (const float*)d_in[11];
    const float* Wx_w    = (const float*)d_in[12];
    const float* Wx_b    = (const float*)d_in[13];
    const float* agg_w   = (const float*)d_in[14];
    const float* agg_b   = (const float*)d_in[15];
    const float* cls_w   = (const float*)d_in[16];
    const float* cls_b   = (const float*)d_in[17];
    const int*   mask_ids= (const int*)d_in[18];
    const int*   src_mask= (const int*)d_in[19];
    float* out = (float*)d_out;

    float *p_seqn, *p_feats, *p_qk, *p_qkw, *p_qkb, *p_adjm, *p_adjc;
    float *p_Ax, *p_node, *p_U, *p_S, *p_vm, *p_bm;
    cudaGetSymbolAddress((void**)&p_seqn,  g_seqn);
    cudaGetSymbolAddress((void**)&p_feats, g_feats);
    cudaGetSymbolAddress((void**)&p_qk,    g_qk);
    cudaGetSymbolAddress((void**)&p_qkw,   g_qkw);
    cudaGetSymbolAddress((void**)&p_qkb,   g_qkb);
    cudaGetSymbolAddress((void**)&p_adjm,  g_adjm);
    cudaGetSymbolAddress((void**)&p_adjc,  g_adjc);
    cudaGetSymbolAddress((void**)&p_Ax,    g_Ax);
    cudaGetSymbolAddress((void**)&p_node,  g_node);
    cudaGetSymbolAddress((void**)&p_U,     g_U);
    cudaGetSymbolAddress((void**)&p_S,     g_S);
    cudaGetSymbolAddress((void**)&p_vm,    g_vm);
    cudaGetSymbolAddress((void**)&p_bm,    g_bm);

    const int MROWS = BB * LL;                 // 8192
    const int ATTN_SMEM = (512 * 28 + 16 * 28 + 512 + 16 * 9) * 4;  // 61760 B
    cudaFuncSetAttribute(attn_kernel, cudaFuncAttributeMaxDynamicSharedMemorySize, ATTN_SMEM);

    pre_kernel<<<80, 256>>>(Wx_w, Wx_b, q_w, q_b, k_w, k_b);
    ln_kernel<<<MROWS, 256>>>(seq, ln_a, ln_b);

    // x -> feats[:, 0:100]
    gemm_nt_tc<<<dim3(1, MROWS / BM), 128>>>(p_seqn, DD, Wxx_w, Wxx_b,
                                             p_feats, 3 * AA, MROWS, AA, DD, 0);
    // q|k combined -> g_qk (ldc=200)
    gemm_nt_tc<<<dim3(2, MROWS / BM), 128>>>(p_feats, 3 * AA, p_qkw, p_qkb,
                                             p_qk, 2 * AA, MROWS, 2 * AA, AA, 0);
    // fused scores + softmax + head folding
    attn_kernel<<<dim3(LL / 16, BB), 256, ATTN_SMEM>>>(syn, src_mask);

    // layer 0: Ax = adjm @ x ; x1 = relu(Ax @ W^T + b) -> feats[:,100:200]
    gemm_nn_b_tc<<<dim3(1, LL / BM, BB), 128>>>(p_adjm, p_feats, 3 * AA, LL * 3 * AA,
                                                p_Ax, AA, LL * AA, AA,
                                                nullptr, nullptr, nullptr, nullptr);
    gemm_nt_tc<<<dim3(1, MROWS / BM), 128>>>(p_Ax, AA, W_w, W_b,
                                             p_feats + AA, 3 * AA, MROWS, AA, AA, 1);
    umvm_su_kernel<<<BB, 256>>>();

    // layer 1: Ax = adjc @ x1 + rank-1 ; x2 = relu(Ax @ W^T + b) -> feats[:,200:300]
    gemm_nn_b_tc<<<dim3(1, LL / BM, BB), 128>>>(p_adjc, p_feats + AA, 3 * AA, LL * 3 * AA,
                                                p_Ax, AA, LL * AA, AA,
                                                p_U, p_S, p_vm, p_bm);
    gemm_nt_tc<<<dim3(1, MROWS / BM), 128>>>(p_Ax, AA, W_w, W_b,
                                             p_feats + 2 * AA, 3 * AA, MROWS, AA, AA, 1);

    // node = relu(feats @ agg^T + b)
    gemm_nt_tc<<<dim3(1, MROWS / BM), 128>>>(p_feats, 3 * AA, agg_w, agg_b,
                                             p_node, AA, MROWS, AA, 3 * AA, 1);

    pool_kernel<<<BB, 128>>>(mask_ids);
    logits_kernel<<<1, 64>>>(cls_w, cls_b, out);
}

// round 6
// speedup vs baseline: 1.5175x; 1.5175x over previous
#include <cuda_runtime.h>
#include <math.h>

#define BB 16
#define LL 512
#define DD 768
#define HH 4
#define AA 100
#define DK 25
#define PP 3
#define EPS 1e-6f

#define BM 32
#define BN 112
#define AST 20
#define BST 20
#define BNNST 120
#define NSTG 3
#define KST 36   // attn K-tile row stride (words): conflict-free float4 phases

// ---------------- scratch ----------------
__device__ float g_seqn[BB * LL * DD];
__device__ float g_feats[BB * LL * 3 * AA];   // [x | x1 | x2], row stride 300
__device__ float g_qk  [BB * LL * 2 * AA];    // [q | k], row stride 200
__device__ float g_qkw [2 * AA * AA];
__device__ float g_qkb [2 * AA];
__device__ float g_adjm[(size_t)BB * LL * LL];
__device__ float g_adjc[(size_t)BB * LL * LL];
__device__ float g_Ax  [BB * LL * AA];
__device__ float g_node[BB * LL * AA];
__device__ float g_pooled[BB * AA];
__device__ float g_cbuf[HH];
__device__ float g_b1m[AA];
__device__ float g_b2m[AA];
__device__ float g_bm[1];
__device__ float g_vm[BB * LL];
__device__ float g_S[BB * AA];
__device__ float g_U[BB * AA];

__device__ __forceinline__ unsigned tf32cvt(float x) {
    unsigned u;
    asm("cvt.rna.tf32.f32 %0, %1;" : "=r"(u) : "f"(x));
    return u;
}
__device__ __forceinline__ void mma_tf32(float* c, unsigned a0, unsigned a1,
                                         unsigned a2, unsigned a3,
                                         unsigned b0, unsigned b1) {
    asm volatile(
        "mma.sync.aligned.m16n8k8.row.col.f32.tf32.tf32.f32 "
        "{%0,%1,%2,%3}, {%4,%5,%6,%7}, {%8,%9}, {%0,%1,%2,%3};"
        : "+f"(c[0]), "+f"(c[1]), "+f"(c[2]), "+f"(c[3])
        : "r"(a0), "r"(a1), "r"(a2), "r"(a3), "r"(b0), "r"(b1));
}
__device__ __forceinline__ void cp16(unsigned dst, const void* src, int bytes) {
    asm volatile("cp.async.cg.shared.global [%0], [%1], 16, %2;\n"
                 :: "r"(dst), "l"(src), "r"(bytes));
}
__device__ __forceinline__ void cp_commit() { asm volatile("cp.async.commit_group;\n"); }
__device__ __forceinline__ void cp_wait1()  { asm volatile("cp.async.wait_group 1;\n"); }

// ---------------- precompute + qk weight packing ----------------
__global__ void pre_kernel(const float* __restrict__ Wx_w, const float* __restrict__ Wx_b,
                           const float* __restrict__ q_w, const float* __restrict__ q_b,
                           const float* __restrict__ k_w, const float* __restrict__ k_b)
{
    int t = threadIdx.x;
    int idx = blockIdx.x * 256 + t;
    if (idx < 2 * AA * AA) {
        int r = idx / AA, c = idx - r * AA;
        g_qkw[idx] = (r < AA) ? q_w[r * AA + c] : k_w[(r - AA) * AA + c];
    }
    if (blockIdx.x == 0) {
        const int LDW = HH + 2 * AA;
        if (t < 2 * AA) g_qkb[t] = (t < AA) ? q_b[t] : k_b[t - AA];
        if (t < HH) {
            float s = 0.f;
            for (int g = 0; g < HH; g++) s += Wx_w[g * LDW + t];
            g_cbuf[t] = s * 0.25f;
        }
        if (t < AA) {
            float s1 = 0.f, s2 = 0.f;
            for (int g = 0; g < HH; g++) {
                s1 += Wx_w[g * LDW + HH + t];
                s2 += Wx_w[g * LDW + HH + AA + t];
            }
            g_b1m[t] = s1 * 0.25f;
            g_b2m[t] = s2 * 0.25f;
        }
        if (t == 0) {
            float s = 0.f;
            for (int g = 0; g < HH; g++) s += Wx_b[g];
            g_bm[0] = s * 0.25f;
        }
    }
}

// ---------------- LayerNorm ----------------
__global__ void ln_kernel(const float* __restrict__ x, const float* __restrict__ a,
                          const float* __restrict__ bvec)
{
    int row = blockIdx.x;
    const float* xr = x + (size_t)row * DD;
    float* yr = g_seqn + (size_t)row * DD;
    int t = threadIdx.x;
    __shared__ float red[16];
    float v0 = xr[t], v1 = xr[t + 256], v2 = xr[t + 512];
    float s = v0 + v1 + v2;
    float ss = v0 * v0 + v1 * v1 + v2 * v2;
    for (int o = 16; o; o >>= 1) {
        s  += __shfl_xor_sync(0xffffffffu, s, o);
        ss += __shfl_xor_sync(0xffffffffu, ss, o);
    }
    int w = t >> 5;
    if ((t & 31) == 0) { red[w] = s; red[8 + w] = ss; }
    __syncthreads();
    float S = 0.f, SS = 0.f;
    #pragma unroll
    for (int i = 0; i < 8; i++) { S += red[i]; SS += red[8 + i]; }
    float mean = S / (float)DD;
    float var = (SS - (float)DD * mean * mean) / (float)(DD - 1);
    var = fmaxf(var, 0.f);
    float inv = 1.f / (sqrtf(var) + EPS);
    yr[t]       = a[t]       * (v0 - mean) * inv + bvec[t];
    yr[t + 256] = a[t + 256] * (v1 - mean) * inv + bvec[t + 256];
    yr[t + 512] = a[t + 512] * (v2 - mean) * inv + bvec[t + 512];
}

// ============ TF32 NT GEMM: C = act(A(M,K; lda) @ B(N,K)^T + bias), ldc ============
__global__ __launch_bounds__(128) void gemm_nt_tc(
    const float* __restrict__ A, int lda,
    const float* __restrict__ Bw, const float* __restrict__ bias,
    float* __restrict__ C, int ldc,
    int M, int N, int K, int act)
{
    __shared__ float As[NSTG][BM * AST];
    __shared__ float Bs[NSTG][BN * BST];
    int t = threadIdx.x;
    int lane = t & 31, warp = t >> 5;
    int wm = warp & 1, wn = warp >> 1;
    int g = lane >> 2, tg = lane & 3;
    int m0 = blockIdx.y * BM, n0 = blockIdx.x * BN;

    unsigned sA = (unsigned)__cvta_generic_to_shared(&As[0][0]);
    unsigned sB = (unsigned)__cvta_generic_to_shared(&Bs[0][0]);

    float acc[7][4];
    #pragma unroll
    for (int j = 0; j < 7; j++)
        #pragma unroll
        for (int i = 0; i < 4; i++) acc[j][i] = 0.f;

    const int arow = t >> 2, ac4 = (t & 3) * 4;
    int nk = (K + 15) >> 4;

    auto issue = [&](int p) {
        int k0 = p << 4;
        int s = p % NSTG;
        int rem = (K - k0 - ac4) * 4;
        int bytes = rem >= 16 ? 16 : (rem > 0 ? rem : 0);
        cp16(sA + (s * BM * AST + arow * AST + ac4) * 4,
             A + (size_t)(m0 + arow) * lda + k0 + ac4, bytes);
        #pragma unroll
        for (int i = 0; i < 4; i++) {
            int idx = t + i * 128;
            if (idx < BN * 4) {
                int row = idx >> 2, c = idx & 3;
                int rem2 = (K - k0 - c * 4) * 4;
                int brow = n0 + row;
                int bytes2 = (brow < N) ? (rem2 >= 16 ? 16 : (rem2 > 0 ? rem2 : 0)) : 0;
                cp16(sB + (s * BN * BST + row * BST + c * 4) * 4,
                     Bw + (size_t)(brow < N ? brow : 0) * K + k0 + c * 4, bytes2);
            }
        }
    };

    issue(0); cp_commit();
    if (nk > 1) issue(1);
    cp_commit();

    for (int it = 0; it < nk; it++) {
        cp_wait1();
        __syncthreads();
        if (it + 2 < nk) issue(it + 2);
        cp_commit();
        int s = it % NSTG;
        const float* as = &As[s][0];
        const float* bs = &Bs[s][0];
        #pragma unroll
        for (int kb = 0; kb < 16; kb += 8) {
            int ar = (wm * 16 + g) * AST + kb + tg;
            unsigned a0 = tf32cvt(as[ar]);
            unsigned a1 = tf32cvt(as[ar + 8 * AST]);
            unsigned a2 = tf32cvt(as[ar + 4]);
            unsigned a3 = tf32cvt(as[ar + 8 * AST + 4]);
            #pragma unroll
            for (int j = 0; j < 7; j++) {
                int br = (wn * 56 + j * 8 + g) * BST + kb + tg;
                unsigned b0 = tf32cvt(bs[br]);
                unsigned b1 = tf32cvt(bs[br + 4]);
                mma_tf32(acc[j], a0, a1, a2, a3, b0, b1);
            }
        }
    }

    int r0 = m0 + wm * 16 + g, r1 = r0 + 8;
    #pragma unroll
    for (int j = 0; j < 7; j++) {
        #pragma unroll
        for (int jj = 0; jj < 2; jj++) {
            int col = n0 + wn * 56 + j * 8 + tg * 2 + jj;
            if (col >= N) continue;
            float bv = bias[col];
            float v0 = acc[j][jj] + bv, v1 = acc[j][2 + jj] + bv;
            if (act) { v0 = fmaxf(v0, 0.f); v1 = fmaxf(v1, 0.f); }
            C[(size_t)r0 * ldc + col] = v0;
            C[(size_t)r1 * ldc + col] = v1;
        }
    }
}

// ============ TF32 batched NN GEMM: C[b] = A[b](512,512) @ B[b](512,N; ldb) + rank-1 ============
__global__ __launch_bounds__(128) void gemm_nn_b_tc(
    const float* __restrict__ Ag, const float* __restrict__ Bg, int ldb, int sB,
    float* __restrict__ Cg, int ldc, int sC, int N,
    const float* __restrict__ U, const float* __restrict__ S,
    const float* __restrict__ vm, const float* __restrict__ bmp)
{
    const int K = LL;
    int b = blockIdx.z;
    const float* A = Ag + (size_t)b * LL * LL;
    const float* Bm = Bg + (size_t)b * sB;
    float* C = Cg + (size_t)b * sC;
    __shared__ float As[NSTG][BM * AST];
    __shared__ float Bs[NSTG][16 * BNNST];
    int t = threadIdx.x;
    int lane = t & 31, warp = t >> 5;
    int wm = warp & 1, wn = warp >> 1;
    int g = lane >> 2, tg = lane & 3;
    int m0 = blockIdx.y * BM;

    unsigned sA = (unsigned)__cvta_generic_to_shared(&As[0][0]);
    unsigned sBs = (unsigned)__cvta_generic_to_shared(&Bs[0][0]);

    float acc[7][4];
    #pragma unroll
    for (int j = 0; j < 7; j++)
        #pragma unroll
        for (int i = 0; i < 4; i++) acc[j][i] = 0.f;

    const int arow = t >> 2, ac4 = (t & 3) * 4;
    int nk = K >> 4;

    auto issue = [&](int p) {
        int k0 = p << 4;
        int s = p % NSTG;
        cp16(sA + (s * BM * AST + arow * AST + ac4) * 4,
             A + (size_t)(m0 + arow) * K + k0 + ac4, 16);
        #pragma unroll
        for (int i = 0; i < 4; i++) {
            int idx = t + i * 128;
            if (idx < 448) {
                int k = idx / 28, c = idx - k * 28;
                int bytes = (c * 4 < N) ? ((N - c * 4) >= 4 ? 16 : (N - c * 4) * 4) : 0;
                cp16(sBs + (s * 16 * BNNST + k * BNNST + c * 4) * 4,
                     Bm + (size_t)(k0 + k) * ldb + c * 4, bytes);
            }
        }
    };

    issue(0); cp_commit();
    issue(1); cp_commit();

    for (int it = 0; it < nk; it++) {
        cp_wait1();
        __syncthreads();
        if (it + 2 < nk) issue(it + 2);
        cp_commit();
        int s = it % NSTG;
        const float* as = &As[s][0];
        const float* bs = &Bs[s][0];
        #pragma unroll
        for (int kb = 0; kb < 16; kb += 8) {
            int ar = (wm * 16 + g) * AST + kb + tg;
            unsigned a0 = tf32cvt(as[ar]);
            unsigned a1 = tf32cvt(as[ar + 8 * AST]);
            unsigned a2 = tf32cvt(as[ar + 4]);
            unsigned a3 = tf32cvt(as[ar + 8 * AST + 4]);
            #pragma unroll
            for (int j = 0; j < 7; j++) {
                int bcol = wn * 56 + j * 8 + g;
                unsigned b0 = tf32cvt(bs[(kb + tg) * BNNST + bcol]);
                unsigned b1 = tf32cvt(bs[(kb + tg + 4) * BNNST + bcol]);
                mma_tf32(acc[j], a0, a1, a2, a3, b0, b1);
            }
        }
    }

    int r0 = m0 + wm * 16 + g, r1 = r0 + 8;
    float e0 = 0.f, e1 = 0.f;
    if (U != nullptr) {
        float bmv = bmp[0];
        e0 = vm[b * LL + r0] + bmv;
        e1 = vm[b * LL + r1] + bmv;
    }
    #pragma unroll
    for (int j = 0; j < 7; j++) {
        #pragma unroll
        for (int jj = 0; jj < 2; jj++) {
            int col = wn * 56 + j * 8 + tg * 2 + jj;
            if (col >= N) continue;
            float v0 = acc[j][jj], v1 = acc[j][2 + jj];
            if (U != nullptr) {
                float uu = U[b * AA + col], ssv = S[b * AA + col];
                v0 += uu + e0 * ssv;
                v1 += uu + e1 * ssv;
            }
            C[(size_t)r0 * ldc + col] = v0;
            C[(size_t)r1 * ldc + col] = v1;
        }
    }
}

// ============ fused scores + softmax + head folding (warp-per-row) ============
// grid (LL/16, BB), 512 threads = 16 warps; warp w handles row i0+w.
// lane owns j = jj*32 + lane -> syn reads & adjm/adjc stores coalesced,
// softmax reductions are pure warp butterflies, per-thread arrays only 16 deep.
__global__ void attn_kernel(const float* __restrict__ syn, const int* __restrict__ src_mask)
{
    extern __shared__ float sm[];
    float* ks = sm;              // 512 * KST words
    float* mk = sm + 512 * KST;  // 512

    int b = blockIdx.y;
    int i0 = blockIdx.x * 16;
    int t = threadIdx.x;
    int warp = t >> 5, lane = t & 31;
    int row = i0 + warp;

    for (int j = t; j < 512; j += 512) mk[j] = src_mask[b * LL + j] ? 0.f : -1e9f;

    float am[16], ac[16];
    #pragma unroll
    for (int jj = 0; jj < 16; jj++) { am[jj] = 0.f; ac[jj] = 0.f; }

    for (int h = 0; h < HH; h++) {
        __syncthreads();
        // K tile: [j][c] with row stride KST=36
        for (int idx = t; idx < 512 * DK; idx += 512) {
            int j = idx / DK, c = idx - j * DK;
            ks[j * KST + c] = g_qk[((size_t)b * LL + j) * 200 + 100 + h * DK + c];
        }
        __syncthreads();

        // q row (broadcast loads within warp)
        float qv[DK];
        const float* qp = g_qk + ((size_t)b * LL + row) * 200 + h * DK;
        #pragma unroll
        for (int c = 0; c < DK; c++) qv[c] = __ldg(qp + c);

        const float* synrow = syn + (((size_t)(b * HH + h)) * LL + row) * LL;
        float ch = g_cbuf[h];

        float sc[16];
        float m = -1e30f;
        #pragma unroll
        for (int jj = 0; jj < 16; jj++) {
            int j = jj * 32 + lane;
            const float4* kp = (const float4*)(ks + j * KST);
            float s = 0.f;
            #pragma unroll
            for (int c = 0; c < 6; c++) {
                float4 k4 = kp[c];
                s += qv[c * 4 + 0] * k4.x + qv[c * 4 + 1] * k4.y
                   + qv[c * 4 + 2] * k4.z + qv[c * 4 + 3] * k4.w;
            }
            s += qv[24] * ks[j * KST + 24];
            float v = s * 0.2f + mk[j] + synrow[j];
            sc[jj] = v;
            m = fmaxf(m, v);
        }
        #pragma unroll
        for (int o = 16; o; o >>= 1) m = fmaxf(m, __shfl_xor_sync(0xffffffffu, m, o));

        float sum = 0.f;
        #pragma unroll
        for (int jj = 0; jj < 16; jj++) {
            float e = __expf(sc[jj] - m);
            sc[jj] = e;
            sum += e;
        }
        #pragma unroll
        for (int o = 16; o; o >>= 1) sum += __shfl_xor_sync(0xffffffffu, sum, o);

        float inv = 1.f / sum;
        #pragma unroll
        for (int jj = 0; jj < 16; jj++) {
            float p = sc[jj] * inv;
            am[jj] += 0.25f * p;
            ac[jj] += ch * p;
        }
    }

    float* amrow = g_adjm + ((size_t)(b * LL) + row) * LL;
    float* acrow = g_adjc + ((size_t)(b * LL) + row) * LL;
    #pragma unroll
    for (int jj = 0; jj < 16; jj++) {
        amrow[jj * 32 + lane] = am[jj];
        acrow[jj * 32 + lane] = ac[jj];
    }
}

// ---------------- merged um/vm + S/U (block per batch) ----------------
__global__ void umvm_su_kernel()
{
    int b = blockIdx.x, t = threadIdx.x, w = t >> 5, lane = t & 31;
    __shared__ float su[LL];
    for (int r = w; r < LL; r += 8) {
        const float* xr = g_feats + ((size_t)(b * LL + r)) * 300 + 100;
        float u = 0.f, v = 0.f;
        for (int c = lane; c < AA; c += 32) {
            float xv = xr[c];
            u += xv * g_b1m[c];
            v += xv * g_b2m[c];
        }
        for (int o = 16; o; o >>= 1) {
            u += __shfl_xor_sync(0xffffffffu, u, o);
            v += __shfl_xor_sync(0xffffffffu, v, o);
        }
        if (lane == 0) { su[r] = u; g_vm[b * LL + r] = v; }
    }
    __syncthreads();
    if (t < AA) {
        float s = 0.f, u = 0.f;
        for (int j = 0; j < LL; j++) {
            float xv = g_feats[((size_t)(b * LL + j)) * 300 + 100 + t];
            s += xv;
            u += su[j] * xv;
        }
        g_S[b * AA + t] = s;
        g_U[b * AA + t] = u;
    }
}

// ---------------- pool ----------------
__global__ void pool_kernel(const int* __restrict__ mask_ids)
{
    int b = blockIdx.x;
    __shared__ int redc[128];
    int t = threadIdx.x;
    int cnt = 0;
    for (int j = t; j < LL; j += 128) cnt += mask_ids[b * LL + j];
    redc[t] = cnt;
    __syncthreads();
    for (int o = 64; o; o >>= 1) { if (t < o) redc[t] += redc[t + o]; __syncthreads(); }
    float vl = fmaxf((float)redc[0], 1.f);
    if (t < AA) {
        float s = 0.f;
        for (int j = 0; j < LL; j++) s += g_node[(size_t)(b * LL + j) * AA + t];
        g_pooled[b * AA + t] = s / vl;
    }
}

// ---------------- logits ----------------
__global__ void logits_kernel(const float* __restrict__ cw, const float* __restrict__ cb,
                              float* __restrict__ out)
{
    int t = threadIdx.x;
    if (t >= BB * PP) return;
    int b = t / PP, p = t % PP;
    float s = cb[p];
    for (int d = 0; d < AA; d++) s += g_pooled[b * AA + d] * cw[p * AA + d];
    out[t] = s;
}

// ================================================================
extern "C" void kernel_launch(void* const* d_in, const int* in_sizes, int n_in,
                              void* d_out, int out_size)
{
    const float* seq     = (const float*)d_in[0];
    const float* syn     = (const float*)d_in[1];
    const float* ln_a    = (const float*)d_in[2];
    const float* ln_b    = (const float*)d_in[3];
    const float* Wxx_w   = (const float*)d_in[4];
    const float* Wxx_b   = (const float*)d_in[5];
    const float* q_w     = (const float*)d_in[6];
    const float* q_b     = (const float*)d_in[7];
    const float* k_w     = (const float*)d_in[8];
    const float* k_b     = (const float*)d_in[9];
    const float* W_w     = (const float*)d_in[10];
    const float* W_b     = (const float*)d_in[11];
    const float* Wx_w    = (const float*)d_in[12];
    const float* Wx_b    = (const float*)d_in[13];
    const float* agg_w   = (const float*)d_in[14];
    const float* agg_b   = (const float*)d_in[15];
    const float* cls_w   = (const float*)d_in[16];
    const float* cls_b   = (const float*)d_in[17];
    const int*   mask_ids= (const int*)d_in[18];
    const int*   src_mask= (const int*)d_in[19];
    float* out = (float*)d_out;

    float *p_seqn, *p_feats, *p_qk, *p_qkw, *p_qkb, *p_adjm, *p_adjc;
    float *p_Ax, *p_node, *p_U, *p_S, *p_vm, *p_bm;
    cudaGetSymbolAddress((void**)&p_seqn,  g_seqn);
    cudaGetSymbolAddress((void**)&p_feats, g_feats);
    cudaGetSymbolAddress((void**)&p_qk,    g_qk);
    cudaGetSymbolAddress((void**)&p_qkw,   g_qkw);
    cudaGetSymbolAddress((void**)&p_qkb,   g_qkb);
    cudaGetSymbolAddress((void**)&p_adjm,  g_adjm);
    cudaGetSymbolAddress((void**)&p_adjc,  g_adjc);
    cudaGetSymbolAddress((void**)&p_Ax,    g_Ax);
    cudaGetSymbolAddress((void**)&p_node,  g_node);
    cudaGetSymbolAddress((void**)&p_U,     g_U);
    cudaGetSymbolAddress((void**)&p_S,     g_S);
    cudaGetSymbolAddress((void**)&p_vm,    g_vm);
    cudaGetSymbolAddress((void**)&p_bm,    g_bm);

    const int MROWS = BB * LL;                     // 8192
    const int ATTN_SMEM = (512 * KST + 512) * 4;   // 75,776 B
    cudaFuncSetAttribute(attn_kernel, cudaFuncAttributeMaxDynamicSharedMemorySize, ATTN_SMEM);

    pre_kernel<<<80, 256>>>(Wx_w, Wx_b, q_w, q_b, k_w, k_b);
    ln_kernel<<<MROWS, 256>>>(seq, ln_a, ln_b);

    // x -> feats[:, 0:100]
    gemm_nt_tc<<<dim3(1, MROWS / BM), 128>>>(p_seqn, DD, Wxx_w, Wxx_b,
                                             p_feats, 3 * AA, MROWS, AA, DD, 0);
    // q|k combined -> g_qk (ldc=200)
    gemm_nt_tc<<<dim3(2, MROWS / BM), 128>>>(p_feats, 3 * AA, p_qkw, p_qkb,
                                             p_qk, 2 * AA, MROWS, 2 * AA, AA, 0);
    // fused scores + softmax + head folding
    attn_kernel<<<dim3(LL / 16, BB), 512, ATTN_SMEM>>>(syn, src_mask);

    // layer 0: Ax = adjm @ x ; x1 = relu(Ax @ W^T + b) -> feats[:,100:200]
    gemm_nn_b_tc<<<dim3(1, LL / BM, BB), 128>>>(p_adjm, p_feats, 3 * AA, LL * 3 * AA,
                                                p_Ax, AA, LL * AA, AA,
                                                nullptr, nullptr, nullptr, nullptr);
    gemm_nt_tc<<<dim3(1, MROWS / BM), 128>>>(p_Ax, AA, W_w, W_b,
                                             p_feats + AA, 3 * AA, MROWS, AA, AA, 1);
    umvm_su_kernel<<<BB, 256>>>();

    // layer 1: Ax = adjc @ x1 + rank-1 ; x2 = relu(Ax @ W^T + b) -> feats[:,200:300]
    gemm_nn_b_tc<<<dim3(1, LL / BM, BB), 128>>>(p_adjc, p_feats + AA, 3 * AA, LL * 3 * AA,
                                                p_Ax, AA, LL * AA, AA,
                                                p_U, p_S, p_vm, p_bm);
    gemm_nt_tc<<<dim3(1, MROWS / BM), 128>>>(p_Ax, AA, W_w, W_b,
                                             p_feats + 2 * AA, 3 * AA, MROWS, AA, AA, 1);

    // node = relu(feats @ agg^T + b)
    gemm_nt_tc<<<dim3(1, MROWS / BM), 128>>>(p_feats, 3 * AA, agg_w, agg_b,
                                             p_node, AA, MROWS, AA, 3 * AA, 1);

    pool_kernel<<<BB, 128>>>(mask_ids);
    logits_kernel<<<1, 64>>>(cls_w, cls_b, out);
}

// round 7
// speedup vs baseline: 2.2443x; 1.4790x over previous
#include <cuda_runtime.h>
#include <math.h>

#define BB 16
#define LL 512
#define DD 768
#define HH 4
#define AA 100
#define DK 25
#define PP 3
#define EPS 1e-6f

#define BM 32
#define BN 112
#define AST 20
#define BST 20
#define BNNST 120
#define NSTG 3
#define KHS 28            // attn per-head K row stride (words)
#define NPART 8           // j-partitions for S/U and pool partials

// ---------------- scratch ----------------
__device__ float g_stats[BB * LL * 2];        // mean, inv per row
__device__ float g_feats[BB * LL * 3 * AA];   // [x | x1 | x2], row stride 300
__device__ float g_qk  [BB * LL * 2 * AA];    // [q | k], row stride 200
__device__ float g_qkw [2 * AA * AA];
__device__ float g_qkb [2 * AA];
__device__ float g_adjm[(size_t)BB * LL * LL];
__device__ float g_adjc[(size_t)BB * LL * LL];
__device__ float g_Ax  [BB * LL * AA];
__device__ float g_node[BB * LL * AA];
__device__ float g_cbuf[HH];
__device__ float g_b1m[AA];
__device__ float g_b2m[AA];
__device__ float g_bm[1];
__device__ float g_um[BB * LL];
__device__ float g_vm[BB * LL];
__device__ float g_Spart[BB * NPART * AA];
__device__ float g_Upart[BB * NPART * AA];
__device__ float g_S[BB * AA];
__device__ float g_U[BB * AA];
__device__ float g_poolpart[BB * NPART * AA];

__device__ __forceinline__ unsigned tf32cvt(float x) {
    unsigned u;
    asm("cvt.rna.tf32.f32 %0, %1;" : "=r"(u) : "f"(x));
    return u;
}
__device__ __forceinline__ void mma_tf32(float* c, unsigned a0, unsigned a1,
                                         unsigned a2, unsigned a3,
                                         unsigned b0, unsigned b1) {
    asm volatile(
        "mma.sync.aligned.m16n8k8.row.col.f32.tf32.tf32.f32 "
        "{%0,%1,%2,%3}, {%4,%5,%6,%7}, {%8,%9}, {%0,%1,%2,%3};"
        : "+f"(c[0]), "+f"(c[1]), "+f"(c[2]), "+f"(c[3])
        : "r"(a0), "r"(a1), "r"(a2), "r"(a3), "r"(b0), "r"(b1));
}
__device__ __forceinline__ void cp16(unsigned dst, const void* src, int bytes) {
    asm volatile("cp.async.cg.shared.global [%0], [%1], 16, %2;\n"
                 :: "r"(dst), "l"(src), "r"(bytes));
}
__device__ __forceinline__ void cp_commit() { asm volatile("cp.async.commit_group;\n"); }
__device__ __forceinline__ void cp_wait1()  { asm volatile("cp.async.wait_group 1;\n"); }

// ---------------- precompute + qk weight packing ----------------
__global__ void pre_kernel(const float* __restrict__ Wx_w, const float* __restrict__ Wx_b,
                           const float* __restrict__ q_w, const float* __restrict__ q_b,
                           const float* __restrict__ k_w, const float* __restrict__ k_b)
{
    int t = threadIdx.x;
    int idx = blockIdx.x * 256 + t;
    if (idx < 2 * AA * AA) {
        int r = idx / AA, c = idx - r * AA;
        g_qkw[idx] = (r < AA) ? q_w[r * AA + c] : k_w[(r - AA) * AA + c];
    }
    if (blockIdx.x == 0) {
        const int LDW = HH + 2 * AA;
        if (t < 2 * AA) g_qkb[t] = (t < AA) ? q_b[t] : k_b[t - AA];
        if (t < HH) {
            float s = 0.f;
            for (int g = 0; g < HH; g++) s += Wx_w[g * LDW + t];
            g_cbuf[t] = s * 0.25f;
        }
        if (t < AA) {
            float s1 = 0.f, s2 = 0.f;
            for (int g = 0; g < HH; g++) {
                s1 += Wx_w[g * LDW + HH + t];
                s2 += Wx_w[g * LDW + HH + AA + t];
            }
            g_b1m[t] = s1 * 0.25f;
            g_b2m[t] = s2 * 0.25f;
        }
        if (t == 0) {
            float s = 0.f;
            for (int g = 0; g < HH; g++) s += Wx_b[g];
            g_bm[0] = s * 0.25f;
        }
    }
}

// ---------------- LN stats: mean + 1/(std+eps) per row ----------------
__global__ void stats_kernel(const float* __restrict__ x)
{
    int row = blockIdx.x;
    const float* xr = x + (size_t)row * DD;
    int t = threadIdx.x;
    __shared__ float red[16];
    float v0 = xr[t], v1 = xr[t + 256], v2 = xr[t + 512];
    float s = v0 + v1 + v2;
    float ss = v0 * v0 + v1 * v1 + v2 * v2;
    for (int o = 16; o; o >>= 1) {
        s  += __shfl_xor_sync(0xffffffffu, s, o);
        ss += __shfl_xor_sync(0xffffffffu, ss, o);
    }
    int w = t >> 5;
    if ((t & 31) == 0) { red[w] = s; red[8 + w] = ss; }
    __syncthreads();
    if (t == 0) {
        float S = 0.f, SS = 0.f;
        #pragma unroll
        for (int i = 0; i < 8; i++) { S += red[i]; SS += red[8 + i]; }
        float mean = S / (float)DD;
        float var = (SS - (float)DD * mean * mean) / (float)(DD - 1);
        var = fmaxf(var, 0.f);
        g_stats[row * 2]     = mean;
        g_stats[row * 2 + 1] = 1.f / (sqrtf(var) + EPS);
    }
}

// ============ LN-fused TF32 NT GEMM: C = A_ln(M,768) @ B(N,768)^T + bias ============
__global__ __launch_bounds__(128) void gemm_ln_tc(
    const float* __restrict__ A,
    const float* __restrict__ Bw, const float* __restrict__ bias,
    const float* __restrict__ lna, const float* __restrict__ lnb,
    float* __restrict__ C, int ldc, int N)
{
    const int K = DD;
    __shared__ float As[NSTG][BM * AST];
    __shared__ float Bs[NSTG][BN * BST];
    int t = threadIdx.x;
    int lane = t & 31, warp = t >> 5;
    int wm = warp & 1, wn = warp >> 1;
    int g = lane >> 2, tg = lane & 3;
    int m0 = blockIdx.y * BM;

    unsigned sA = (unsigned)__cvta_generic_to_shared(&As[0][0]);
    unsigned sB = (unsigned)__cvta_generic_to_shared(&Bs[0][0]);

    float acc[7][4];
    #pragma unroll
    for (int j = 0; j < 7; j++)
        #pragma unroll
        for (int i = 0; i < 4; i++) acc[j][i] = 0.f;

    // stats for my two output rows
    int r0 = m0 + wm * 16 + g, r1 = r0 + 8;
    float mean0 = g_stats[r0 * 2], inv0 = g_stats[r0 * 2 + 1];
    float mean1 = g_stats[r1 * 2], inv1 = g_stats[r1 * 2 + 1];

    const int arow = t >> 2, ac4 = (t & 3) * 4;
    int nk = K >> 4;   // 48

    auto issue = [&](int p) {
        int k0 = p << 4;
        int s = p % NSTG;
        cp16(sA + (s * BM * AST + arow * AST + ac4) * 4,
             A + (size_t)(m0 + arow) * K + k0 + ac4, 16);
        #pragma unroll
        for (int i = 0; i < 4; i++) {
            int idx = t + i * 128;
            if (idx < BN * 4) {
                int row = idx >> 2, c = idx & 3;
                int bytes = (row < N) ? 16 : 0;
                cp16(sB + (s * BN * BST + row * BST + c * 4) * 4,
                     Bw + (size_t)(row < N ? row : 0) * K + k0 + c * 4, bytes);
            }
        }
    };

    issue(0); cp_commit();
    issue(1); cp_commit();

    for (int it = 0; it < nk; it++) {
        cp_wait1();
        __syncthreads();
        if (it + 2 < nk) issue(it + 2);
        cp_commit();
        int s = it % NSTG;
        const float* as = &As[s][0];
        const float* bs = &Bs[s][0];
        #pragma unroll
        for (int kb = 0; kb < 16; kb += 8) {
            int kg0 = it * 16 + kb + tg;
            float la0 = __ldg(lna + kg0), lb0 = __ldg(lnb + kg0);
            float la1 = __ldg(lna + kg0 + 4), lb1 = __ldg(lnb + kg0 + 4);
            int ar = (wm * 16 + g) * AST + kb + tg;
            unsigned a0 = tf32cvt(fmaf((as[ar] - mean0) * inv0, la0, lb0));
            unsigned a1 = tf32cvt(fmaf((as[ar + 8 * AST] - mean1) * inv1, la0, lb0));
            unsigned a2 = tf32cvt(fmaf((as[ar + 4] - mean0) * inv0, la1, lb1));
            unsigned a3 = tf32cvt(fmaf((as[ar + 8 * AST + 4] - mean1) * inv1, la1, lb1));
            #pragma unroll
            for (int j = 0; j < 7; j++) {
                int br = (wn * 56 + j * 8 + g) * BST + kb + tg;
                unsigned b0 = tf32cvt(bs[br]);
                unsigned b1 = tf32cvt(bs[br + 4]);
                mma_tf32(acc[j], a0, a1, a2, a3, b0, b1);
            }
        }
    }

    #pragma unroll
    for (int j = 0; j < 7; j++) {
        #pragma unroll
        for (int jj = 0; jj < 2; jj++) {
            int col = wn * 56 + j * 8 + tg * 2 + jj;
            if (col >= N) continue;
            float bv = bias[col];
            C[(size_t)r0 * ldc + col] = acc[j][jj] + bv;
            C[(size_t)r1 * ldc + col] = acc[j][2 + jj] + bv;
        }
    }
}

// ============ TF32 NT GEMM: C = act(A(M,K; lda) @ B(N,K)^T + bias), ldc ============
__global__ __launch_bounds__(128) void gemm_nt_tc(
    const float* __restrict__ A, int lda,
    const float* __restrict__ Bw, const float* __restrict__ bias,
    float* __restrict__ C, int ldc,
    int M, int N, int K, int act)
{
    __shared__ float As[NSTG][BM * AST];
    __shared__ float Bs[NSTG][BN * BST];
    int t = threadIdx.x;
    int lane = t & 31, warp = t >> 5;
    int wm = warp & 1, wn = warp >> 1;
    int g = lane >> 2, tg = lane & 3;
    int m0 = blockIdx.y * BM, n0 = blockIdx.x * BN;

    unsigned sA = (unsigned)__cvta_generic_to_shared(&As[0][0]);
    unsigned sB = (unsigned)__cvta_generic_to_shared(&Bs[0][0]);

    float acc[7][4];
    #pragma unroll
    for (int j = 0; j < 7; j++)
        #pragma unroll
        for (int i = 0; i < 4; i++) acc[j][i] = 0.f;

    const int arow = t >> 2, ac4 = (t & 3) * 4;
    int nk = (K + 15) >> 4;

    auto issue = [&](int p) {
        int k0 = p << 4;
        int s = p % NSTG;
        int rem = (K - k0 - ac4) * 4;
        int bytes = rem >= 16 ? 16 : (rem > 0 ? rem : 0);
        cp16(sA + (s * BM * AST + arow * AST + ac4) * 4,
             A + (size_t)(m0 + arow) * lda + k0 + ac4, bytes);
        #pragma unroll
        for (int i = 0; i < 4; i++) {
            int idx = t + i * 128;
            if (idx < BN * 4) {
                int row = idx >> 2, c = idx & 3;
                int rem2 = (K - k0 - c * 4) * 4;
                int brow = n0 + row;
                int bytes2 = (brow < N) ? (rem2 >= 16 ? 16 : (rem2 > 0 ? rem2 : 0)) : 0;
                cp16(sB + (s * BN * BST + row * BST + c * 4) * 4,
                     Bw + (size_t)(brow < N ? brow : 0) * K + k0 + c * 4, bytes2);
            }
        }
    };

    issue(0); cp_commit();
    if (nk > 1) issue(1);
    cp_commit();

    for (int it = 0; it < nk; it++) {
        cp_wait1();
        __syncthreads();
        if (it + 2 < nk) issue(it + 2);
        cp_commit();
        int s = it % NSTG;
        const float* as = &As[s][0];
        const float* bs = &Bs[s][0];
        #pragma unroll
        for (int kb = 0; kb < 16; kb += 8) {
            int ar = (wm * 16 + g) * AST + kb + tg;
            unsigned a0 = tf32cvt(as[ar]);
            unsigned a1 = tf32cvt(as[ar + 8 * AST]);
            unsigned a2 = tf32cvt(as[ar + 4]);
            unsigned a3 = tf32cvt(as[ar + 8 * AST + 4]);
            #pragma unroll
            for (int j = 0; j < 7; j++) {
                int br = (wn * 56 + j * 8 + g) * BST + kb + tg;
                unsigned b0 = tf32cvt(bs[br]);
                unsigned b1 = tf32cvt(bs[br + 4]);
                mma_tf32(acc[j], a0, a1, a2, a3, b0, b1);
            }
        }
    }

    int r0 = m0 + wm * 16 + g, r1 = r0 + 8;
    #pragma unroll
    for (int j = 0; j < 7; j++) {
        #pragma unroll
        for (int jj = 0; jj < 2; jj++) {
            int col = n0 + wn * 56 + j * 8 + tg * 2 + jj;
            if (col >= N) continue;
            float bv = bias[col];
            float v0 = acc[j][jj] + bv, v1 = acc[j][2 + jj] + bv;
            if (act) { v0 = fmaxf(v0, 0.f); v1 = fmaxf(v1, 0.f); }
            C[(size_t)r0 * ldc + col] = v0;
            C[(size_t)r1 * ldc + col] = v1;
        }
    }
}

// ============ TF32 batched NN GEMM: C[b] = A[b](512,512) @ B[b](512,N; ldb) + rank-1 ============
__global__ __launch_bounds__(128) void gemm_nn_b_tc(
    const float* __restrict__ Ag, const float* __restrict__ Bg, int ldb, int sB,
    float* __restrict__ Cg, int ldc, int sC, int N,
    const float* __restrict__ U, const float* __restrict__ S,
    const float* __restrict__ vm, const float* __restrict__ bmp)
{
    const int K = LL;
    int b = blockIdx.z;
    const float* A = Ag + (size_t)b * LL * LL;
    const float* Bm = Bg + (size_t)b * sB;
    float* C = Cg + (size_t)b * sC;
    __shared__ float As[NSTG][BM * AST];
    __shared__ float Bs[NSTG][16 * BNNST];
    int t = threadIdx.x;
    int lane = t & 31, warp = t >> 5;
    int wm = warp & 1, wn = warp >> 1;
    int g = lane >> 2, tg = lane & 3;
    int m0 = blockIdx.y * BM;

    unsigned sA = (unsigned)__cvta_generic_to_shared(&As[0][0]);
    unsigned sBs = (unsigned)__cvta_generic_to_shared(&Bs[0][0]);

    float acc[7][4];
    #pragma unroll
    for (int j = 0; j < 7; j++)
        #pragma unroll
        for (int i = 0; i < 4; i++) acc[j][i] = 0.f;

    const int arow = t >> 2, ac4 = (t & 3) * 4;
    int nk = K >> 4;

    auto issue = [&](int p) {
        int k0 = p << 4;
        int s = p % NSTG;
        cp16(sA + (s * BM * AST + arow * AST + ac4) * 4,
             A + (size_t)(m0 + arow) * K + k0 + ac4, 16);
        #pragma unroll
        for (int i = 0; i < 4; i++) {
            int idx = t + i * 128;
            if (idx < 448) {
                int k = idx / 28, c = idx - k * 28;
                int bytes = (c * 4 < N) ? ((N - c * 4) >= 4 ? 16 : (N - c * 4) * 4) : 0;
                cp16(sBs + (s * 16 * BNNST + k * BNNST + c * 4) * 4,
                     Bm + (size_t)(k0 + k) * ldb + c * 4, bytes);
            }
        }
    };

    issue(0); cp_commit();
    issue(1); cp_commit();

    for (int it = 0; it < nk; it++) {
        cp_wait1();
        __syncthreads();
        if (it + 2 < nk) issue(it + 2);
        cp_commit();
        int s = it % NSTG;
        const float* as = &As[s][0];
        const float* bs = &Bs[s][0];
        #pragma unroll
        for (int kb = 0; kb < 16; kb += 8) {
            int ar = (wm * 16 + g) * AST + kb + tg;
            unsigned a0 = tf32cvt(as[ar]);
            unsigned a1 = tf32cvt(as[ar + 8 * AST]);
            unsigned a2 = tf32cvt(as[ar + 4]);
            unsigned a3 = tf32cvt(as[ar + 8 * AST + 4]);
            #pragma unroll
            for (int j = 0; j < 7; j++) {
                int bcol = wn * 56 + j * 8 + g;
                unsigned b0 = tf32cvt(bs[(kb + tg) * BNNST + bcol]);
                unsigned b1 = tf32cvt(bs[(kb + tg + 4) * BNNST + bcol]);
                mma_tf32(acc[j], a0, a1, a2, a3, b0, b1);
            }
        }
    }

    int r0 = m0 + wm * 16 + g, r1 = r0 + 8;
    float e0 = 0.f, e1 = 0.f;
    if (U != nullptr) {
        float bmv = bmp[0];
        e0 = vm[b * LL + r0] + bmv;
        e1 = vm[b * LL + r1] + bmv;
    }
    #pragma unroll
    for (int j = 0; j < 7; j++) {
        #pragma unroll
        for (int jj = 0; jj < 2; jj++) {
            int col = wn * 56 + j * 8 + tg * 2 + jj;
            if (col >= N) continue;
            float v0 = acc[j][jj], v1 = acc[j][2 + jj];
            if (U != nullptr) {
                float uu = U[b * AA + col], ssv = S[b * AA + col];
                v0 += uu + e0 * ssv;
                v1 += uu + e1 * ssv;
            }
            C[(size_t)r0 * ldc + col] = v0;
            C[(size_t)r1 * ldc + col] = v1;
        }
    }
}

// ============ fused attention: single K-load for all 4 heads ============
// grid (LL/16, BB), 512 threads = 16 warps (warp = row); smem = 4 head regions
// of 512 rows x KHS(28) words; per-head stride 28 -> conflict-free float4 phases.
__global__ void attn_kernel(const float* __restrict__ syn, const int* __restrict__ src_mask)
{
    extern __shared__ float ks[];   // 4 * 512 * KHS words = 229376 B

    int b = blockIdx.y;
    int i0 = blockIdx.x * 16;
    int t = threadIdx.x;
    int warp = t >> 5, lane = t & 31;
    int row = i0 + warp;

    // mask in registers (per-lane j ownership)
    float mkr[16];
    #pragma unroll
    for (int jj = 0; jj < 16; jj++)
        mkr[jj] = src_mask[b * LL + jj * 32 + lane] ? 0.f : -1e9f;

    // load K for all 4 heads once
    for (int idx = t; idx < 512 * 100; idx += 512) {
        int j = idx / 100, c = idx - j * 100;
        int h = c / 25, cc = c - h * 25;
        ks[h * 512 * KHS + j * KHS + cc] = g_qk[((size_t)b * LL + j) * 200 + 100 + c];
    }
    __syncthreads();

    float am[16], ac[16];
    #pragma unroll
    for (int jj = 0; jj < 16; jj++) { am[jj] = 0.f; ac[jj] = 0.f; }

    for (int h = 0; h < HH; h++) {
        float qv[DK];
        const float* qp = g_qk + ((size_t)b * LL + row) * 200 + h * DK;
        #pragma unroll
        for (int c = 0; c < DK; c++) qv[c] = __ldg(qp + c);

        const float* synrow = syn + (((size_t)(b * HH + h)) * LL + row) * LL;
        const float* kh = ks + h * 512 * KHS;
        float ch = g_cbuf[h];

        float sc[16];
        float m = -1e30f;
        #pragma unroll
        for (int jj = 0; jj < 16; jj++) {
            int j = jj * 32 + lane;
            const float4* kp = (const float4*)(kh + j * KHS);
            float s = 0.f;
            #pragma unroll
            for (int c = 0; c < 6; c++) {
                float4 k4 = kp[c];
                s += qv[c * 4 + 0] * k4.x + qv[c * 4 + 1] * k4.y
                   + qv[c * 4 + 2] * k4.z + qv[c * 4 + 3] * k4.w;
            }
            s += qv[24] * kh[j * KHS + 24];
            float v = s * 0.2f + mkr[jj] + synrow[j];
            sc[jj] = v;
            m = fmaxf(m, v);
        }
        #pragma unroll
        for (int o = 16; o; o >>= 1) m = fmaxf(m, __shfl_xor_sync(0xffffffffu, m, o));

        float sum = 0.f;
        #pragma unroll
        for (int jj = 0; jj < 16; jj++) {
            float e = __expf(sc[jj] - m);
            sc[jj] = e;
            sum += e;
        }
        #pragma unroll
        for (int o = 16; o; o >>= 1) sum += __shfl_xor_sync(0xffffffffu, sum, o);

        float inv = 1.f / sum;
        #pragma unroll
        for (int jj = 0; jj < 16; jj++) {
            float p = sc[jj] * inv;
            am[jj] += 0.25f * p;
            ac[jj] += ch * p;
        }
    }

    float* amrow = g_adjm + ((size_t)(b * LL) + row) * LL;
    float* acrow = g_adjc + ((size_t)(b * LL) + row) * LL;
    #pragma unroll
    for (int jj = 0; jj < 16; jj++) {
        amrow[jj * 32 + lane] = am[jj];
        acrow[jj * 32 + lane] = ac[jj];
    }
}

// ---------------- um/vm: warp-per-row, full-chip ----------------
__global__ void umvm_kernel()
{
    int w = threadIdx.x >> 5, lane = threadIdx.x & 31;
    int row = blockIdx.x * 8 + w;   // grid 1024
    const float* xr = g_feats + ((size_t)row) * 300 + 100;
    float u = 0.f, v = 0.f;
    #pragma unroll
    for (int c4 = 0; c4 < 4; c4++) {
        int c = c4 * 32 + lane;
        if (c < AA) {
            float xv = xr[c];
            u += xv * g_b1m[c];
            v += xv * g_b2m[c];
        }
    }
    for (int o = 16; o; o >>= 1) {
        u += __shfl_xor_sync(0xffffffffu, u, o);
        v += __shfl_xor_sync(0xffffffffu, v, o);
    }
    if (lane == 0) { g_um[row] = u; g_vm[row] = v; }
}

// ---------------- S/U partials over j chunks ----------------
__global__ void su_part_kernel()
{
    int b = blockIdx.x, part = blockIdx.y;
    int t = threadIdx.x;
    if (t >= AA) return;
    int j0 = part * (LL / NPART);
    float s = 0.f, u = 0.f;
    for (int j = j0; j < j0 + LL / NPART; j++) {
        float xv = g_feats[((size_t)(b * LL + j)) * 300 + 100 + t];
        s += xv;
        u += g_um[b * LL + j] * xv;
    }
    g_Spart[(b * NPART + part) * AA + t] = s;
    g_Upart[(b * NPART + part) * AA + t] = u;
}

__global__ void su_reduce_kernel()
{
    int b = blockIdx.x, t = threadIdx.x;
    if (t >= AA) return;
    float s = 0.f, u = 0.f;
    #pragma unroll
    for (int p = 0; p < NPART; p++) {
        s += g_Spart[(b * NPART + p) * AA + t];
        u += g_Upart[(b * NPART + p) * AA + t];
    }
    g_S[b * AA + t] = s;
    g_U[b * AA + t] = u;
}

// ---------------- pool partials ----------------
__global__ void pool_part_kernel()
{
    int b = blockIdx.x, part = blockIdx.y;
    int t = threadIdx.x;
    if (t >= AA) return;
    int j0 = part * (LL / NPART);
    float s = 0.f;
    for (int j = j0; j < j0 + LL / NPART; j++)
        s += g_node[(size_t)(b * LL + j) * AA + t];
    g_poolpart[(b * NPART + part) * AA + t] = s;
}

// ---------------- final: reduce pool + valid_len + logits ----------------
__global__ void logits_kernel(const int* __restrict__ mask_ids,
                              const float* __restrict__ cw, const float* __restrict__ cb,
                              float* __restrict__ out)
{
    __shared__ float pooled[BB * AA];
    __shared__ float vls[BB];
    int t = threadIdx.x;   // 512
    int warp = t >> 5, lane = t & 31;
    for (int idx = t; idx < BB * AA; idx += 512) {
        int b = idx / AA, d = idx - b * AA;
        float s = 0.f;
        #pragma unroll
        for (int p = 0; p < NPART; p++) s += g_poolpart[(b * NPART + p) * AA + d];
        pooled[idx] = s;
    }
    if (warp < BB) {
        int cnt = 0;
        #pragma unroll
        for (int i = 0; i < 16; i++) cnt += mask_ids[warp * LL + i * 32 + lane];
        for (int o = 16; o; o >>= 1) cnt += __shfl_xor_sync(0xffffffffu, cnt, o);
        if (lane == 0) vls[warp] = fmaxf((float)cnt, 1.f);
    }
    __syncthreads();
    if (t < BB * PP) {
        int b = t / PP, p = t - b * PP;
        float s = 0.f;
        for (int d = 0; d < AA; d++) s += pooled[b * AA + d] * cw[p * AA + d];
        out[t] = s / vls[b] + cb[p];
    }
}

// ================================================================
extern "C" void kernel_launch(void* const* d_in, const int* in_sizes, int n_in,
                              void* d_out, int out_size)
{
    const float* seq     = (const float*)d_in[0];
    const float* syn     = (const float*)d_in[1];
    const float* ln_a    = (const float*)d_in[2];
    const float* ln_b    = (const float*)d_in[3];
    const float* Wxx_w   = (const float*)d_in[4];
    const float* Wxx_b   = (const float*)d_in[5];
    const float* q_w     = (const float*)d_in[6];
    const float* q_b     = (const float*)d_in[7];
    const float* k_w     = (const float*)d_in[8];
    const float* k_b     = (const float*)d_in[9];
    const float* W_w     = (const float*)d_in[10];
    const float* W_b     = (const float*)d_in[11];
    const float* Wx_w    = (const float*)d_in[12];
    const float* Wx_b    = (const float*)d_in[13];
    const float* agg_w   = (const float*)d_in[14];
    const float* agg_b   = (const float*)d_in[15];
    const float* cls_w   = (const float*)d_in[16];
    const float* cls_b   = (const float*)d_in[17];
    const int*   mask_ids= (const int*)d_in[18];
    const int*   src_mask= (const int*)d_in[19];
    float* out = (float*)d_out;

    float *p_feats, *p_qk, *p_qkw, *p_qkb, *p_adjm, *p_adjc;
    float *p_Ax, *p_node, *p_U, *p_S, *p_vm, *p_bm;
    cudaGetSymbolAddress((void**)&p_feats, g_feats);
    cudaGetSymbolAddress((void**)&p_qk,    g_qk);
    cudaGetSymbolAddress((void**)&p_qkw,   g_qkw);
    cudaGetSymbolAddress((void**)&p_qkb,   g_qkb);
    cudaGetSymbolAddress((void**)&p_adjm,  g_adjm);
    cudaGetSymbolAddress((void**)&p_adjc,  g_adjc);
    cudaGetSymbolAddress((void**)&p_Ax,    g_Ax);
    cudaGetSymbolAddress((void**)&p_node,  g_node);
    cudaGetSymbolAddress((void**)&p_U,     g_U);
    cudaGetSymbolAddress((void**)&p_S,     g_S);
    cudaGetSymbolAddress((void**)&p_vm,    g_vm);
    cudaGetSymbolAddress((void**)&p_bm,    g_bm);

    const int MROWS = BB * LL;                    // 8192
    const int ATTN_SMEM = 4 * 512 * KHS * 4;      // 229,376 B
    cudaFuncSetAttribute(attn_kernel, cudaFuncAttributeMaxDynamicSharedMemorySize, ATTN_SMEM);

    pre_kernel<<<80, 256>>>(Wx_w, Wx_b, q_w, q_b, k_w, k_b);
    stats_kernel<<<MROWS, 256>>>(seq);

    // x = LN(seq) @ Wxx^T + b  -> feats[:, 0:100]   (LN fused)
    gemm_ln_tc<<<dim3(1, MROWS / BM), 128>>>(seq, Wxx_w, Wxx_b, ln_a, ln_b,
                                             p_feats, 3 * AA, AA);
    // q|k -> g_qk (ldc=200)
    gemm_nt_tc<<<dim3(2, MROWS / BM), 128>>>(p_feats, 3 * AA, p_qkw, p_qkb,
                                             p_qk, 2 * AA, MROWS, 2 * AA, AA, 0);
    // fused scores + softmax + head folding
    attn_kernel<<<dim3(LL / 16, BB), 512, ATTN_SMEM>>>(syn, src_mask);

    // layer 0
    gemm_nn_b_tc<<<dim3(1, LL / BM, BB), 128>>>(p_adjm, p_feats, 3 * AA, LL * 3 * AA,
                                                p_Ax, AA, LL * AA, AA,
                                                nullptr, nullptr, nullptr, nullptr);
    gemm_nt_tc<<<dim3(1, MROWS / BM), 128>>>(p_Ax, AA, W_w, W_b,
                                             p_feats + AA, 3 * AA, MROWS, AA, AA, 1);
    umvm_kernel<<<MROWS / 8, 256>>>();
    su_part_kernel<<<dim3(BB, NPART), 128>>>();
    su_reduce_kernel<<<BB, 128>>>();

    // layer 1
    gemm_nn_b_tc<<<dim3(1, LL / BM, BB), 128>>>(p_adjc, p_feats + AA, 3 * AA, LL * 3 * AA,
                                                p_Ax, AA, LL * AA, AA,
                                                p_U, p_S, p_vm, p_bm);
    gemm_nt_tc<<<dim3(1, MROWS / BM), 128>>>(p_Ax, AA, W_w, W_b,
                                             p_feats + 2 * AA, 3 * AA, MROWS, AA, AA, 1);

    // node = relu(feats @ agg^T + b)
    gemm_nt_tc<<<dim3(1, MROWS / BM), 128>>>(p_feats, 3 * AA, agg_w, agg_b,
                                             p_node, AA, MROWS, AA, 3 * AA, 1);

    pool_part_kernel<<<dim3(BB, NPART), 128>>>();
    logits_kernel<<<1, 512>>>(mask_ids, cls_w, cls_b, out);
}